// round 15
// baseline (speedup 1.0000x reference)
#include <cuda_runtime.h>
#include <cuda_bf16.h>
#include <cuda_fp16.h>
#include <stdint.h>

#define NPTS 1024
#define NTH  512
#define THR2 0.09f

typedef unsigned long long u64;

// ---------------- smem byte-offset map (GCN kernel) ----------------
// OFF_B dual use: x1 fp16 [1024][64] rows (j*128B), then in-place
// B fragments (fp16): [k16(64)][nt(8)][lane(32)][8B] = 128KB
#define OFF_B     0
#define OFF_PX    131072
#define OFF_PY    135168
#define OFF_DINV  139264
#define OFF_SX    143360
#define OFF_SY    147456
#define OFF_W2    151552   // 16KB
#define OFF_W1    167936   // 512B
#define OFF_B1    168448
#define OFF_B2    168704
#define OFF_CS    168960
#define OFF_GV    169216
#define OFF_BINOF 169472   // 1024 u8: bin of sorted point
#define OFF_BINST 170496   // 10 ints
#define OFF_CNT   170536   // 9 ints
#define OFF_CNT2  170572   // 9 ints
#define OFF_BKM   170608   // 9 u64 (8B aligned)
#define SMEM_GCN  170688

// ---------------- GRU smem map (dynamic) ----------------
#define GOFF_WHH  0        // 32*384 u64 = 98304 B, [c2][row]
#define GOFF_H    98304    // 128 f32
#define GOFF_GH   98816    // 384 f32
#define GOFF_GI   100352   // 384 f32
#define GOFF_HS   101888   // 128 f32
#define SMEM_GRU  102400

__device__ float g_gi[128 * 384];

// ---------------- helpers ----------------
__device__ __forceinline__ uint32_t smem_u32(const void* p) {
    uint32_t a;
    asm("{ .reg .u64 t; cvta.to.shared.u64 t, %1; cvt.u32.u64 %0, t; }" : "=r"(a) : "l"(p));
    return a;
}
__device__ __forceinline__ u64 pack2f(float a, float b) {
    u64 r; asm("mov.b64 %0, {%1, %2};" : "=l"(r) : "f"(a), "f"(b)); return r;
}
__device__ __forceinline__ u64 ld2(const float* p) {
    float2 v = *(const float2*)p;
    return pack2f(v.x, v.y);
}
#define FMA2(acc, a, b) asm("fma.rn.f32x2 %0, %1, %2, %0;" : "+l"(acc) : "l"(a), "l"(b))
__device__ __forceinline__ u64 add2(u64 a, u64 b) {
    u64 r; asm("add.rn.f32x2 %0, %1, %2;" : "=l"(r) : "l"(a), "l"(b)); return r;
}
__device__ __forceinline__ u64 fma2v(u64 a, u64 b, u64 c) {
    u64 r; asm("fma.rn.f32x2 %0, %1, %2, %3;" : "=l"(r) : "l"(a), "l"(b), "l"(c)); return r;
}
// pack two f32 into f16x2: lo = a (even k), hi = b (odd k)
__device__ __forceinline__ uint32_t cvt_f16x2(float a, float b) {
    uint32_t r;
    asm("cvt.rn.f16x2.f32 %0, %1, %2;" : "=r"(r) : "f"(b), "f"(a));
    return r;
}
// mask pair: fp16x2 {adj(i,j0), adj(i,j1)}; u = dx^2 + dy^2 - thr2, neighbor <=> sign(u)
__device__ __forceinline__ uint32_t maskpair(u64 px2, u64 py2, u64 nx2, u64 ny2,
                                             u64 one2, u64 nthr2) {
    u64 dx, dy, u;
    asm("fma.rn.f32x2 %0, %1, %2, %3;" : "=l"(dx) : "l"(px2), "l"(one2), "l"(nx2));
    asm("fma.rn.f32x2 %0, %1, %2, %3;" : "=l"(dy) : "l"(py2), "l"(one2), "l"(ny2));
    asm("fma.rn.f32x2 %0, %1, %1, %2;" : "=l"(u)  : "l"(dy), "l"(nthr2));
    asm("fma.rn.f32x2 %0, %1, %1, %0;" : "+l"(u)  : "l"(dx));
    uint32_t lo, hi, m;
    asm("mov.b64 {%0, %1}, %2;" : "=r"(lo), "=r"(hi) : "l"(u));
    asm("prmt.b32 %0, %1, %2, 0xFFBB;" : "=r"(m) : "r"(lo), "r"(hi));
    return m & 0x3C003C00u;
}
__device__ __forceinline__ void mma_f16(float* d, uint32_t a0, uint32_t a1,
                                        uint32_t a2, uint32_t a3,
                                        uint32_t b0, uint32_t b1) {
    asm("mma.sync.aligned.m16n8k16.row.col.f32.f16.f16.f32 "
        "{%0,%1,%2,%3}, {%4,%5,%6,%7}, {%8,%9}, {%0,%1,%2,%3};"
        : "+f"(d[0]), "+f"(d[1]), "+f"(d[2]), "+f"(d[3])
        : "r"(a0), "r"(a1), "r"(a2), "r"(a3), "r"(b0), "r"(b1));
}
__device__ __forceinline__ uint32_t neigh9(int b) {
    int by = b / 3, bx = b - by * 3;
    int y0 = by > 0 ? by - 1 : 0, y1 = by < 2 ? by + 1 : 2;
    int x0 = bx > 0 ? bx - 1 : 0, x1 = bx < 2 ? bx + 1 : 2;
    uint32_t m = 0;
    for (int yy = y0; yy <= y1; yy++)
        for (int xx = x0; xx <= x1; xx++) m |= 1u << (yy * 3 + xx);
    return m;
}

// ---------------- GCN kernel (r11-exact, measured 160.6us) ----------------
__global__ void __launch_bounds__(NTH, 1) gcn_kernel(
    const float* __restrict__ points,
    const float* __restrict__ W1, const float* __restrict__ b1,
    const float* __restrict__ W2, const float* __restrict__ b2,
    const float* __restrict__ Wg, const float* __restrict__ bg,
    const float* __restrict__ Wih, const float* __restrict__ bih)
{
    extern __shared__ char smem[];
    float* px   = (float*)(smem + OFF_PX);
    float* py   = (float*)(smem + OFF_PY);
    float* dinv = (float*)(smem + OFF_DINV);
    float* sx   = (float*)(smem + OFF_SX);
    float* sy   = (float*)(smem + OFF_SY);
    float* w2s  = (float*)(smem + OFF_W2);
    float* w1s  = (float*)(smem + OFF_W1);
    float* b1s  = (float*)(smem + OFF_B1);
    float* b2s  = (float*)(smem + OFF_B2);
    float* colsum = (float*)(smem + OFF_CS);
    float* gcnv   = (float*)(smem + OFF_GV);
    uint8_t* binof = (uint8_t*)(smem + OFF_BINOF);
    int* binstart  = (int*)(smem + OFF_BINST);
    int* counts    = (int*)(smem + OFF_CNT);
    int* cnt2      = (int*)(smem + OFF_CNT2);
    u64* bkm       = (u64*)(smem + OFF_BKM);

    const int g    = blockIdx.x;
    const int tid  = threadIdx.x;
    const int lane = tid & 31;
    const int warp = tid >> 5;

    const float* pts = points + (size_t)g * NPTS * 2;
    for (int j = tid; j < NPTS; j += NTH) {
        float2 p = ((const float2*)pts)[j];
        sx[j] = p.x; sy[j] = p.y;
    }
    for (int i = tid; i < 128; i += NTH)  w1s[i] = W1[i];
    for (int i = tid; i < 4096; i += NTH) w2s[i] = W2[i];
    if (tid < 64) { b1s[tid] = b1[tid]; b2s[tid] = b2[tid]; colsum[tid] = 0.f; }
    if (tid < 9) { counts[tid] = 0; cnt2[tid] = 0; }
    __syncthreads();

    for (int ig = 0; ig < 2; ig++) {
        int j = tid + ig * NTH;
        int bx = (int)(sx[j] * 3.0f); bx = bx > 2 ? 2 : bx;
        int by = (int)(sy[j] * 3.0f); by = by > 2 ? 2 : by;
        atomicAdd(&counts[by * 3 + bx], 1);
    }
    __syncthreads();
    if (tid == 0) {
        int acc = 0;
        for (int b = 0; b < 9; b++) { binstart[b] = acc; acc += counts[b]; }
        binstart[9] = acc;
    }
    __syncthreads();

    for (int ig = 0; ig < 2; ig++) {
        int j = tid + ig * NTH;
        float x = sx[j], y = sy[j];
        int bx = (int)(x * 3.0f); bx = bx > 2 ? 2 : bx;
        int by = (int)(y * 3.0f); by = by > 2 ? 2 : by;
        int b = by * 3 + bx;
        int rank = binstart[b] + atomicAdd(&cnt2[b], 1);
        px[rank] = x; py[rank] = y;
        binof[rank] = (uint8_t)b;
    }
    __syncthreads();

    if (tid < 9) {
        uint32_t alw = neigh9(tid);
        u64 m = 0;
        for (int k = 0; k < 64; k++) {
            int c0 = binof[k * 16], c1 = binof[k * 16 + 15];
            uint32_t rng = ((2u << c1) - 1u) & ~((1u << c0) - 1u);
            if (alw & rng) m |= 1ull << k;
        }
        bkm[tid] = m;
    }

    const u64 one2  = pack2f(1.f, 1.f);
    const u64 nthr2 = pack2f(-THR2, -THR2);
    const u64* pxp = (const u64*)px;
    const u64* pyp = (const u64*)py;
    __syncthreads();

    // ---- degree pass over adjacent-bin bands (exact fp16x2 count) ----
    for (int ig = 0; ig < 2; ig++) {
        int i = tid + ig * NTH;
        int b = binof[i];
        int by = b / 3, bx = b - by * 3;
        int y0 = by > 0 ? by - 1 : 0, y1 = by < 2 ? by + 1 : 2;
        int x0 = bx > 0 ? bx - 1 : 0, x1 = bx < 2 ? bx + 1 : 2;
        u64 nxi = pack2f(-px[i], -px[i]);
        u64 nyi = pack2f(-py[i], -py[i]);
        uint32_t acc_h = 0;
        if (bx == 1) {
            int lp = binstart[y0 * 3] >> 1;
            int hp = (binstart[y1 * 3 + 3] + 1) >> 1;
            #pragma unroll 4
            for (int jp = lp; jp < hp; jp++) {
                uint32_t m = maskpair(pxp[jp], pyp[jp], nxi, nyi, one2, nthr2);
                asm("add.rn.f16x2 %0, %0, %1;" : "+r"(acc_h) : "r"(m));
            }
        } else {
            int last = -1;
            for (int band = y0; band <= y1; band++) {
                int lp = binstart[band * 3 + x0] >> 1;
                if (lp <= last) lp = last + 1;
                int hp = (binstart[band * 3 + x1 + 1] + 1) >> 1;
                #pragma unroll 4
                for (int jp = lp; jp < hp; jp++) {
                    uint32_t m = maskpair(pxp[jp], pyp[jp], nxi, nyi, one2, nthr2);
                    asm("add.rn.f16x2 %0, %0, %1;" : "+r"(acc_h) : "r"(m));
                }
                if (hp - 1 > last) last = hp - 1;
            }
        }
        __half2 h2 = *(__half2*)&acc_h;
        float cnt = __low2float(h2) + __high2float(h2);
        dinv[i] = rsqrtf(cnt);
    }
    __syncthreads();

    // ---- s pass: s = An @ pts over adjacent-bin bands ----
    const u64* dvp = (const u64*)dinv;
    for (int ig = 0; ig < 2; ig++) {
        int i = tid + ig * NTH;
        int b = binof[i];
        int by = b / 3, bx = b - by * 3;
        int y0 = by > 0 ? by - 1 : 0, y1 = by < 2 ? by + 1 : 2;
        int x0 = bx > 0 ? bx - 1 : 0, x1 = bx < 2 ? bx + 1 : 2;
        u64 nxi = pack2f(-px[i], -px[i]);
        u64 nyi = pack2f(-py[i], -py[i]);
        u64 ax2 = 0ULL, ay2 = 0ULL;
        int lp0, hp0, lp1, hp1, lp2, hp2;
        if (bx == 1) {
            lp0 = binstart[y0 * 3] >> 1;
            hp0 = (binstart[y1 * 3 + 3] + 1) >> 1;
            lp1 = 0; hp1 = 0; lp2 = 0; hp2 = 0;
        } else {
            int last = -1;
            int lp[3] = {0,0,0}, hp[3] = {0,0,0};
            int nb = 0;
            for (int band = y0; band <= y1; band++) {
                int l = binstart[band * 3 + x0] >> 1;
                if (l <= last) l = last + 1;
                int h = (binstart[band * 3 + x1 + 1] + 1) >> 1;
                lp[nb] = l; hp[nb] = h; nb++;
                if (h - 1 > last) last = h - 1;
            }
            lp0 = lp[0]; hp0 = hp[0]; lp1 = lp[1]; hp1 = hp[1]; lp2 = lp[2]; hp2 = hp[2];
        }
        #pragma unroll 1
        for (int seg = 0; seg < 3; seg++) {
            int lp = seg == 0 ? lp0 : (seg == 1 ? lp1 : lp2);
            int hp = seg == 0 ? hp0 : (seg == 1 ? hp1 : hp2);
            #pragma unroll 4
            for (int jp = lp; jp < hp; jp++) {
                u64 px2 = pxp[jp], py2 = pyp[jp];
                u64 dx2 = add2(px2, nxi);
                u64 dy2 = add2(py2, nyi);
                u64 u = fma2v(dy2, dy2, nthr2);
                FMA2(u, dx2, dx2);
                uint32_t mlo = (uint32_t)(((int32_t)(uint32_t)u) >> 31);
                uint32_t mhi = (uint32_t)(((int32_t)(uint32_t)(u >> 32)) >> 31);
                u64 dv = dvp[jp];
                u64 m2 = (u64)((uint32_t)dv & mlo) | (((u64)((uint32_t)(dv >> 32) & mhi)) << 32);
                FMA2(ax2, m2, px2);
                FMA2(ay2, m2, py2);
            }
        }
        float axl, axh, ayl, ayh;
        asm("mov.b64 {%0, %1}, %2;" : "=f"(axl), "=f"(axh) : "l"(ax2));
        asm("mov.b64 {%0, %1}, %2;" : "=f"(ayl), "=f"(ayh) : "l"(ay2));
        float di = dinv[i];
        sx[i] = di * (axl + axh);
        sy[i] = di * (ayl + ayh);
    }
    __syncthreads();

    // ---- B-build phase 1: x1 fp16 rows into OFF_B ----
    #pragma unroll 1
    for (int half = 0; half < 2; half++) {
        int j = tid + half * 512;
        float s0 = sx[j], s1 = sy[j], dj = dinv[j];
        uint32_t row[32];
        #pragma unroll
        for (int k2 = 0; k2 < 32; k2++) {
            float a = fmaxf(fmaf(s0, w1s[4*k2],   fmaf(s1, w1s[4*k2+1], b1s[2*k2])),   0.f) * dj;
            float b = fmaxf(fmaf(s0, w1s[4*k2+2], fmaf(s1, w1s[4*k2+3], b1s[2*k2+1])), 0.f) * dj;
            row[k2] = cvt_f16x2(a, b);
        }
        uint4* dst = (uint4*)(smem + OFF_B + j * 128);
        #pragma unroll
        for (int q = 0; q < 8; q++)
            dst[q] = make_uint4(row[4*q], row[4*q+1], row[4*q+2], row[4*q+3]);
    }
    __syncthreads();

    // ---- B-build phase 2: w = x1 @ W2^T via HMMA, in-place scatter ----
    {
        uint32_t Wf[8][4][2];
        {
            int m = (lane >> 2);
            int kq = (lane & 3) * 2;
            #pragma unroll
            for (int nt = 0; nt < 8; nt++) {
                const float* wr = w2s + (nt * 8 + m) * 64;
                #pragma unroll
                for (int s = 0; s < 4; s++) {
                    float2 klo = *(const float2*)(wr + s * 16 + kq);
                    float2 khi = *(const float2*)(wr + s * 16 + kq + 8);
                    Wf[nt][s][0] = cvt_f16x2(klo.x, klo.y);
                    Wf[nt][s][1] = cvt_f16x2(khi.x, khi.y);
                }
            }
        }
        const uint32_t a_base = smem_u32(smem) + OFF_B + (lane & 15) * 128 + (lane >> 4) * 16;
        const int r0 = lane >> 2;
        #pragma unroll 1
        for (int jb = warp * 4; jb < warp * 4 + 4; jb++) {
            uint32_t Af[4][4];
            #pragma unroll
            for (int s = 0; s < 4; s++) {
                asm volatile(
                    "ldmatrix.sync.aligned.m8n8.x4.shared.b16 {%0,%1,%2,%3}, [%4];"
                    : "=r"(Af[s][0]), "=r"(Af[s][1]), "=r"(Af[s][2]), "=r"(Af[s][3])
                    : "r"(a_base + jb * 2048 + s * 32));
            }
            float D[8][4] = {};
            #pragma unroll
            for (int s = 0; s < 4; s++)
                #pragma unroll
                for (int nt = 0; nt < 8; nt++)
                    mma_f16(D[nt], Af[s][0], Af[s][1], Af[s][2], Af[s][3],
                            Wf[nt][s][0], Wf[nt][s][1]);
            #pragma unroll
            for (int nt = 0; nt < 8; nt++) {
                int m0 = nt * 8 + (lane & 3) * 2;
                #pragma unroll
                for (int q = 0; q < 4; q++) {
                    int r = r0 + (q >> 1) * 8;
                    int m = m0 + (q & 1);
                    int off = OFF_B + jb * 2048 + nt * 256 + (m & 7) * 32
                            + ((r & 7) >> 1) * 8 + (r >> 3) * 4 + (r & 1) * 2;
                    *(__half*)(smem + off) = __float2half(D[nt][q]);
                }
            }
        }
    }
    __syncthreads();

    // ---- MMA phase: 2 row-passes x (2 mt x 8 nt), k16 skip ----
    const int g4 = lane >> 2;
    float cs[8][2] = {};

    #pragma unroll 1
    for (int rp = 0; rp < 2; rp++) {
        const int R = rp * 512 + warp * 32;

        u64 kmask = 0;
        {
            int rb0 = binof[R], rb1 = binof[R + 31];
            for (int b = rb0; b <= rb1; b++) kmask |= bkm[b];
        }

        u64 npx[4], npy[4];
        #pragma unroll
        for (int q = 0; q < 4; q++) {
            int i = R + (q >> 1) * 16 + g4 + (q & 1) * 8;
            npx[q] = pack2f(-px[i], -px[i]);
            npy[q] = pack2f(-py[i], -py[i]);
        }

        float acc[2][8][4] = {};
        #pragma unroll 1
        for (int k16 = 0; k16 < 64; k16++) {
            if (!((kmask >> k16) & 1ull)) continue;
            int jA = k16 * 16 + (lane & 3) * 2;
            u64 pax = ld2(px + jA),     pay = ld2(py + jA);
            u64 pbx = ld2(px + jA + 8), pby = ld2(py + jA + 8);

            uint32_t A[2][4];
            #pragma unroll
            for (int mt = 0; mt < 2; mt++) {
                A[mt][0] = maskpair(pax, pay, npx[mt*2],   npy[mt*2],   one2, nthr2);
                A[mt][1] = maskpair(pax, pay, npx[mt*2+1], npy[mt*2+1], one2, nthr2);
                A[mt][2] = maskpair(pbx, pby, npx[mt*2],   npy[mt*2],   one2, nthr2);
                A[mt][3] = maskpair(pbx, pby, npx[mt*2+1], npy[mt*2+1], one2, nthr2);
            }
            #pragma unroll
            for (int nt = 0; nt < 8; nt++) {
                uint2 bv = *(const uint2*)(smem + OFF_B + k16 * 2048 + nt * 256 + lane * 8);
                mma_f16(acc[0][nt], A[0][0], A[0][1], A[0][2], A[0][3], bv.x, bv.y);
                mma_f16(acc[1][nt], A[1][0], A[1][1], A[1][2], A[1][3], bv.x, bv.y);
            }
        }

        #pragma unroll
        for (int mt = 0; mt < 2; mt++) {
            float di0 = dinv[R + mt*16 + g4];
            float di1 = dinv[R + mt*16 + g4 + 8];
            #pragma unroll
            for (int nt = 0; nt < 8; nt++) {
                int col0 = nt * 8 + (lane & 3) * 2;
                float b20 = b2s[col0], b21 = b2s[col0 + 1];
                cs[nt][0] += fmaxf(fmaf(di0, acc[mt][nt][0], b20), 0.f);
                cs[nt][1] += fmaxf(fmaf(di0, acc[mt][nt][1], b21), 0.f);
                cs[nt][0] += fmaxf(fmaf(di1, acc[mt][nt][2], b20), 0.f);
                cs[nt][1] += fmaxf(fmaf(di1, acc[mt][nt][3], b21), 0.f);
            }
        }
    }

    #pragma unroll
    for (int nt = 0; nt < 8; nt++)
        #pragma unroll
        for (int p = 0; p < 2; p++) {
            float v = cs[nt][p];
            v += __shfl_xor_sync(0xffffffffu, v, 4);
            v += __shfl_xor_sync(0xffffffffu, v, 8);
            v += __shfl_xor_sync(0xffffffffu, v, 16);
            if (lane < 4)
                atomicAdd(&colsum[nt * 8 + lane * 2 + p], v);
        }
    __syncthreads();

    if (tid < 64) {
        float acc2 = bg[tid];
        const float inv = 1.0f / 1024.f;
        #pragma unroll 8
        for (int m = 0; m < 64; m++)
            acc2 = fmaf(colsum[m] * inv, Wg[tid * 64 + m], acc2);
        gcnv[tid] = acc2;
    }
    __syncthreads();
    if (tid < 384) {
        float acc2 = bih[tid];
        const float* wr = Wih + tid * 64;
        #pragma unroll 8
        for (int c2 = 0; c2 < 64; c2++)
            acc2 = fmaf(wr[c2], gcnv[c2], acc2);
        g_gi[g * 384 + tid] = acc2;
    }
}

// ---------------- GRU kernel: hybrid Whh (half regs / half smem) ----------------
__global__ void __launch_bounds__(384, 1) gru_kernel(
    const float* __restrict__ Whh, const float* __restrict__ bhh,
    const float* __restrict__ Wf,  const float* __restrict__ bf,
    float* __restrict__ out)
{
    extern __shared__ char smg[];
    u64*   whh2   = (u64*)(smg + GOFF_WHH);     // [c2(32)][row(384)], k in [64,128)
    float* h      = (float*)(smg + GOFF_H);
    float* gh_s   = (float*)(smg + GOFF_GH);
    float* gi_s   = (float*)(smg + GOFF_GI);
    float* hsum_s = (float*)(smg + GOFF_HS);

    const int b   = blockIdx.x;
    const int tid = threadIdx.x;

    // rows' k[0,64) in registers (32 u64 = 64 regs); k[64,128) to smem
    u64 wreg[32];
    const u64* wg = (const u64*)Whh;
    #pragma unroll
    for (int c2 = 0; c2 < 32; c2++) wreg[c2] = wg[tid * 64 + c2];
    #pragma unroll
    for (int c2 = 0; c2 < 32; c2++) whh2[c2 * 384 + tid] = wg[tid * 64 + 32 + c2];

    if (tid < 128) h[tid] = 0.f;
    const float bhh_r = bhh[tid];
    const float* gib = g_gi + (size_t)b * 32 * 384;
    float gi_cur = gib[tid];
    float hsum = 0.f;
    __syncthreads();

    for (int t = 0; t < 32; t++) {
        float gi_nxt = (t < 31) ? gib[(t + 1) * 384 + tid] : 0.f;
        gi_s[tid] = gi_cur;

        // gh[tid] = Whh[tid].h + bhh[tid]; two 32-FMA2 chains (reg half + smem half)
        u64 a0 = pack2f(bhh_r, 0.f), a1 = 0ULL;
        const double2* hv4 = (const double2*)h;
        #pragma unroll
        for (int c4 = 0; c4 < 16; c4++) {
            double2 hv = hv4[c4];
            FMA2(a0, wreg[2*c4],     __double_as_longlong(hv.x));
            FMA2(a1, wreg[2*c4 + 1], __double_as_longlong(hv.y));
        }
        #pragma unroll
        for (int c4 = 0; c4 < 16; c4++) {
            double2 hv = hv4[16 + c4];
            u64 w0 = whh2[(2*c4)     * 384 + tid];
            u64 w1 = whh2[(2*c4 + 1) * 384 + tid];
            FMA2(a0, w0, __double_as_longlong(hv.x));
            FMA2(a1, w1, __double_as_longlong(hv.y));
        }
        u64 stot = add2(a0, a1);
        float alo, ahi;
        asm("mov.b64 {%0, %1}, %2;" : "=f"(alo), "=f"(ahi) : "l"(stot));
        gh_s[tid] = alo + ahi;
        __syncthreads();

        if (tid < 128) {
            float rg = 1.f / (1.f + __expf(-(gi_s[tid]       + gh_s[tid])));
            float zg = 1.f / (1.f + __expf(-(gi_s[128 + tid] + gh_s[128 + tid])));
            float ng = tanhf(gi_s[256 + tid] + rg * gh_s[256 + tid]);
            float hn = (1.f - zg) * ng + zg * h[tid];
            h[tid] = hn;
            hsum += hn;
        }
        __syncthreads();
        gi_cur = gi_nxt;
    }

    if (tid < 128) hsum_s[tid] = hsum;
    __syncthreads();
    if (tid < 2) {
        float acc = bf[tid];
        const float inv = 1.0f / 32.f;
        #pragma unroll 8
        for (int c = 0; c < 128; c++)
            acc = fmaf(Wf[tid * 128 + c], hsum_s[c] * inv, acc);
        out[b * 2 + tid] = acc;
    }
}

extern "C" void kernel_launch(void* const* d_in, const int* in_sizes, int n_in,
                              void* d_out, int out_size) {
    const float* points = (const float*)d_in[0];
    const float* W1  = (const float*)d_in[1];
    const float* b1  = (const float*)d_in[2];
    const float* W2  = (const float*)d_in[3];
    const float* b2  = (const float*)d_in[4];
    const float* Wg  = (const float*)d_in[5];
    const float* bg  = (const float*)d_in[6];
    const float* Wih = (const float*)d_in[7];
    const float* Whh = (const float*)d_in[8];
    const float* bih = (const float*)d_in[9];
    const float* bhh = (const float*)d_in[10];
    const float* Wf  = (const float*)d_in[11];
    const float* bf  = (const float*)d_in[12];
    float* out = (float*)d_out;

    cudaFuncSetAttribute(gcn_kernel, cudaFuncAttributeMaxDynamicSharedMemorySize, SMEM_GCN);
    cudaFuncSetAttribute(gru_kernel, cudaFuncAttributeMaxDynamicSharedMemorySize, SMEM_GRU);

    gcn_kernel<<<128, NTH, SMEM_GCN>>>(points, W1, b1, W2, b2, Wg, bg, Wih, bih);
    gru_kernel<<<4, 384, SMEM_GRU>>>(Whh, bhh, Wf, bf, out);
}

// round 16
// speedup vs baseline: 1.0510x; 1.0510x over previous
#include <cuda_runtime.h>
#include <cuda_bf16.h>
#include <cuda_fp16.h>
#include <stdint.h>

#define NPTS 1024
#define NTH  512
#define THR2 0.09f

typedef unsigned long long u64;

// ---------------- smem byte-offset map (GCN kernel) ----------------
// OFF_B dual use: x1 fp16 [1024][64] rows (j*128B), then in-place
// B fragments (fp16): [k16(64)][nt(8)][lane(32)][8B] = 128KB
#define OFF_B     0
#define OFF_PX    131072
#define OFF_PY    135168
#define OFF_DINV  139264
#define OFF_SX    143360
#define OFF_SY    147456
#define OFF_W2    151552   // 16KB
#define OFF_W1    167936   // 512B
#define OFF_B1    168448
#define OFF_B2    168704
#define OFF_CS    168960
#define OFF_GV    169216
#define OFF_BINOF 169472   // 1024 u8: bin of sorted point
#define OFF_BINST 170496   // 10 ints
#define OFF_CNT   170536   // 9 ints
#define OFF_CNT2  170572   // 9 ints
#define OFF_BKM   170608   // 9 u64 (8B aligned)
#define SMEM_GCN  170688

__device__ float g_gi[128 * 384];

// ---------------- helpers ----------------
__device__ __forceinline__ uint32_t smem_u32(const void* p) {
    uint32_t a;
    asm("{ .reg .u64 t; cvta.to.shared.u64 t, %1; cvt.u32.u64 %0, t; }" : "=r"(a) : "l"(p));
    return a;
}
__device__ __forceinline__ u64 pack2f(float a, float b) {
    u64 r; asm("mov.b64 %0, {%1, %2};" : "=l"(r) : "f"(a), "f"(b)); return r;
}
__device__ __forceinline__ u64 ld2(const float* p) {
    float2 v = *(const float2*)p;
    return pack2f(v.x, v.y);
}
#define FMA2(acc, a, b) asm("fma.rn.f32x2 %0, %1, %2, %0;" : "+l"(acc) : "l"(a), "l"(b))
__device__ __forceinline__ u64 add2(u64 a, u64 b) {
    u64 r; asm("add.rn.f32x2 %0, %1, %2;" : "=l"(r) : "l"(a), "l"(b)); return r;
}
__device__ __forceinline__ u64 fma2v(u64 a, u64 b, u64 c) {
    u64 r; asm("fma.rn.f32x2 %0, %1, %2, %3;" : "=l"(r) : "l"(a), "l"(b), "l"(c)); return r;
}
// pack two f32 into f16x2: lo = a (even k), hi = b (odd k)
__device__ __forceinline__ uint32_t cvt_f16x2(float a, float b) {
    uint32_t r;
    asm("cvt.rn.f16x2.f32 %0, %1, %2;" : "=r"(r) : "f"(b), "f"(a));
    return r;
}
// mask pair: fp16x2 {adj(i,j0), adj(i,j1)}; u = dx^2 + dy^2 - thr2, neighbor <=> sign(u)
__device__ __forceinline__ uint32_t maskpair(u64 px2, u64 py2, u64 nx2, u64 ny2,
                                             u64 one2, u64 nthr2) {
    u64 dx, dy, u;
    asm("fma.rn.f32x2 %0, %1, %2, %3;" : "=l"(dx) : "l"(px2), "l"(one2), "l"(nx2));
    asm("fma.rn.f32x2 %0, %1, %2, %3;" : "=l"(dy) : "l"(py2), "l"(one2), "l"(ny2));
    asm("fma.rn.f32x2 %0, %1, %1, %2;" : "=l"(u)  : "l"(dy), "l"(nthr2));
    asm("fma.rn.f32x2 %0, %1, %1, %0;" : "+l"(u)  : "l"(dx));
    uint32_t lo, hi, m;
    asm("mov.b64 {%0, %1}, %2;" : "=r"(lo), "=r"(hi) : "l"(u));
    asm("prmt.b32 %0, %1, %2, 0xFFBB;" : "=r"(m) : "r"(lo), "r"(hi));
    return m & 0x3C003C00u;
}
__device__ __forceinline__ void mma_f16(float* d, uint32_t a0, uint32_t a1,
                                        uint32_t a2, uint32_t a3,
                                        uint32_t b0, uint32_t b1) {
    asm("mma.sync.aligned.m16n8k16.row.col.f32.f16.f16.f32 "
        "{%0,%1,%2,%3}, {%4,%5,%6,%7}, {%8,%9}, {%0,%1,%2,%3};"
        : "+f"(d[0]), "+f"(d[1]), "+f"(d[2]), "+f"(d[3])
        : "r"(a0), "r"(a1), "r"(a2), "r"(a3), "r"(b0), "r"(b1));
}
__device__ __forceinline__ uint32_t neigh9(int b) {
    int by = b / 3, bx = b - by * 3;
    int y0 = by > 0 ? by - 1 : 0, y1 = by < 2 ? by + 1 : 2;
    int x0 = bx > 0 ? bx - 1 : 0, x1 = bx < 2 ? bx + 1 : 2;
    uint32_t m = 0;
    for (int yy = y0; yy <= y1; yy++)
        for (int xx = x0; xx <= x1; xx++) m |= 1u << (yy * 3 + xx);
    return m;
}

// ---------------- GCN kernel (r11-exact, frozen) ----------------
__global__ void __launch_bounds__(NTH, 1) gcn_kernel(
    const float* __restrict__ points,
    const float* __restrict__ W1, const float* __restrict__ b1,
    const float* __restrict__ W2, const float* __restrict__ b2,
    const float* __restrict__ Wg, const float* __restrict__ bg,
    const float* __restrict__ Wih, const float* __restrict__ bih)
{
    extern __shared__ char smem[];
    float* px   = (float*)(smem + OFF_PX);
    float* py   = (float*)(smem + OFF_PY);
    float* dinv = (float*)(smem + OFF_DINV);
    float* sx   = (float*)(smem + OFF_SX);
    float* sy   = (float*)(smem + OFF_SY);
    float* w2s  = (float*)(smem + OFF_W2);
    float* w1s  = (float*)(smem + OFF_W1);
    float* b1s  = (float*)(smem + OFF_B1);
    float* b2s  = (float*)(smem + OFF_B2);
    float* colsum = (float*)(smem + OFF_CS);
    float* gcnv   = (float*)(smem + OFF_GV);
    uint8_t* binof = (uint8_t*)(smem + OFF_BINOF);
    int* binstart  = (int*)(smem + OFF_BINST);
    int* counts    = (int*)(smem + OFF_CNT);
    int* cnt2      = (int*)(smem + OFF_CNT2);
    u64* bkm       = (u64*)(smem + OFF_BKM);

    const int g    = blockIdx.x;
    const int tid  = threadIdx.x;
    const int lane = tid & 31;
    const int warp = tid >> 5;

    const float* pts = points + (size_t)g * NPTS * 2;
    for (int j = tid; j < NPTS; j += NTH) {
        float2 p = ((const float2*)pts)[j];
        sx[j] = p.x; sy[j] = p.y;
    }
    for (int i = tid; i < 128; i += NTH)  w1s[i] = W1[i];
    for (int i = tid; i < 4096; i += NTH) w2s[i] = W2[i];
    if (tid < 64) { b1s[tid] = b1[tid]; b2s[tid] = b2[tid]; colsum[tid] = 0.f; }
    if (tid < 9) { counts[tid] = 0; cnt2[tid] = 0; }
    __syncthreads();

    for (int ig = 0; ig < 2; ig++) {
        int j = tid + ig * NTH;
        int bx = (int)(sx[j] * 3.0f); bx = bx > 2 ? 2 : bx;
        int by = (int)(sy[j] * 3.0f); by = by > 2 ? 2 : by;
        atomicAdd(&counts[by * 3 + bx], 1);
    }
    __syncthreads();
    if (tid == 0) {
        int acc = 0;
        for (int b = 0; b < 9; b++) { binstart[b] = acc; acc += counts[b]; }
        binstart[9] = acc;
    }
    __syncthreads();

    for (int ig = 0; ig < 2; ig++) {
        int j = tid + ig * NTH;
        float x = sx[j], y = sy[j];
        int bx = (int)(x * 3.0f); bx = bx > 2 ? 2 : bx;
        int by = (int)(y * 3.0f); by = by > 2 ? 2 : by;
        int b = by * 3 + bx;
        int rank = binstart[b] + atomicAdd(&cnt2[b], 1);
        px[rank] = x; py[rank] = y;
        binof[rank] = (uint8_t)b;
    }
    __syncthreads();

    if (tid < 9) {
        uint32_t alw = neigh9(tid);
        u64 m = 0;
        for (int k = 0; k < 64; k++) {
            int c0 = binof[k * 16], c1 = binof[k * 16 + 15];
            uint32_t rng = ((2u << c1) - 1u) & ~((1u << c0) - 1u);
            if (alw & rng) m |= 1ull << k;
        }
        bkm[tid] = m;
    }

    const u64 one2  = pack2f(1.f, 1.f);
    const u64 nthr2 = pack2f(-THR2, -THR2);
    const u64* pxp = (const u64*)px;
    const u64* pyp = (const u64*)py;
    __syncthreads();

    // ---- degree pass over adjacent-bin bands (exact fp16x2 count) ----
    for (int ig = 0; ig < 2; ig++) {
        int i = tid + ig * NTH;
        int b = binof[i];
        int by = b / 3, bx = b - by * 3;
        int y0 = by > 0 ? by - 1 : 0, y1 = by < 2 ? by + 1 : 2;
        int x0 = bx > 0 ? bx - 1 : 0, x1 = bx < 2 ? bx + 1 : 2;
        u64 nxi = pack2f(-px[i], -px[i]);
        u64 nyi = pack2f(-py[i], -py[i]);
        uint32_t acc_h = 0;
        if (bx == 1) {
            int lp = binstart[y0 * 3] >> 1;
            int hp = (binstart[y1 * 3 + 3] + 1) >> 1;
            #pragma unroll 4
            for (int jp = lp; jp < hp; jp++) {
                uint32_t m = maskpair(pxp[jp], pyp[jp], nxi, nyi, one2, nthr2);
                asm("add.rn.f16x2 %0, %0, %1;" : "+r"(acc_h) : "r"(m));
            }
        } else {
            int last = -1;
            for (int band = y0; band <= y1; band++) {
                int lp = binstart[band * 3 + x0] >> 1;
                if (lp <= last) lp = last + 1;
                int hp = (binstart[band * 3 + x1 + 1] + 1) >> 1;
                #pragma unroll 4
                for (int jp = lp; jp < hp; jp++) {
                    uint32_t m = maskpair(pxp[jp], pyp[jp], nxi, nyi, one2, nthr2);
                    asm("add.rn.f16x2 %0, %0, %1;" : "+r"(acc_h) : "r"(m));
                }
                if (hp - 1 > last) last = hp - 1;
            }
        }
        __half2 h2 = *(__half2*)&acc_h;
        float cnt = __low2float(h2) + __high2float(h2);
        dinv[i] = rsqrtf(cnt);
    }
    __syncthreads();

    // ---- s pass: s = An @ pts over adjacent-bin bands ----
    const u64* dvp = (const u64*)dinv;
    for (int ig = 0; ig < 2; ig++) {
        int i = tid + ig * NTH;
        int b = binof[i];
        int by = b / 3, bx = b - by * 3;
        int y0 = by > 0 ? by - 1 : 0, y1 = by < 2 ? by + 1 : 2;
        int x0 = bx > 0 ? bx - 1 : 0, x1 = bx < 2 ? bx + 1 : 2;
        u64 nxi = pack2f(-px[i], -px[i]);
        u64 nyi = pack2f(-py[i], -py[i]);
        u64 ax2 = 0ULL, ay2 = 0ULL;
        int lp0, hp0, lp1, hp1, lp2, hp2;
        if (bx == 1) {
            lp0 = binstart[y0 * 3] >> 1;
            hp0 = (binstart[y1 * 3 + 3] + 1) >> 1;
            lp1 = 0; hp1 = 0; lp2 = 0; hp2 = 0;
        } else {
            int last = -1;
            int lp[3] = {0,0,0}, hp[3] = {0,0,0};
            int nb = 0;
            for (int band = y0; band <= y1; band++) {
                int l = binstart[band * 3 + x0] >> 1;
                if (l <= last) l = last + 1;
                int h = (binstart[band * 3 + x1 + 1] + 1) >> 1;
                lp[nb] = l; hp[nb] = h; nb++;
                if (h - 1 > last) last = h - 1;
            }
            lp0 = lp[0]; hp0 = hp[0]; lp1 = lp[1]; hp1 = hp[1]; lp2 = lp[2]; hp2 = hp[2];
        }
        #pragma unroll 1
        for (int seg = 0; seg < 3; seg++) {
            int lp = seg == 0 ? lp0 : (seg == 1 ? lp1 : lp2);
            int hp = seg == 0 ? hp0 : (seg == 1 ? hp1 : hp2);
            #pragma unroll 4
            for (int jp = lp; jp < hp; jp++) {
                u64 px2 = pxp[jp], py2 = pyp[jp];
                u64 dx2 = add2(px2, nxi);
                u64 dy2 = add2(py2, nyi);
                u64 u = fma2v(dy2, dy2, nthr2);
                FMA2(u, dx2, dx2);
                uint32_t mlo = (uint32_t)(((int32_t)(uint32_t)u) >> 31);
                uint32_t mhi = (uint32_t)(((int32_t)(uint32_t)(u >> 32)) >> 31);
                u64 dv = dvp[jp];
                u64 m2 = (u64)((uint32_t)dv & mlo) | (((u64)((uint32_t)(dv >> 32) & mhi)) << 32);
                FMA2(ax2, m2, px2);
                FMA2(ay2, m2, py2);
            }
        }
        float axl, axh, ayl, ayh;
        asm("mov.b64 {%0, %1}, %2;" : "=f"(axl), "=f"(axh) : "l"(ax2));
        asm("mov.b64 {%0, %1}, %2;" : "=f"(ayl), "=f"(ayh) : "l"(ay2));
        float di = dinv[i];
        sx[i] = di * (axl + axh);
        sy[i] = di * (ayl + ayh);
    }
    __syncthreads();

    // ---- B-build phase 1: x1 fp16 rows into OFF_B ----
    #pragma unroll 1
    for (int half = 0; half < 2; half++) {
        int j = tid + half * 512;
        float s0 = sx[j], s1 = sy[j], dj = dinv[j];
        uint32_t row[32];
        #pragma unroll
        for (int k2 = 0; k2 < 32; k2++) {
            float a = fmaxf(fmaf(s0, w1s[4*k2],   fmaf(s1, w1s[4*k2+1], b1s[2*k2])),   0.f) * dj;
            float b = fmaxf(fmaf(s0, w1s[4*k2+2], fmaf(s1, w1s[4*k2+3], b1s[2*k2+1])), 0.f) * dj;
            row[k2] = cvt_f16x2(a, b);
        }
        uint4* dst = (uint4*)(smem + OFF_B + j * 128);
        #pragma unroll
        for (int q = 0; q < 8; q++)
            dst[q] = make_uint4(row[4*q], row[4*q+1], row[4*q+2], row[4*q+3]);
    }
    __syncthreads();

    // ---- B-build phase 2: w = x1 @ W2^T via HMMA, in-place scatter ----
    {
        uint32_t Wf[8][4][2];
        {
            int m = (lane >> 2);
            int kq = (lane & 3) * 2;
            #pragma unroll
            for (int nt = 0; nt < 8; nt++) {
                const float* wr = w2s + (nt * 8 + m) * 64;
                #pragma unroll
                for (int s = 0; s < 4; s++) {
                    float2 klo = *(const float2*)(wr + s * 16 + kq);
                    float2 khi = *(const float2*)(wr + s * 16 + kq + 8);
                    Wf[nt][s][0] = cvt_f16x2(klo.x, klo.y);
                    Wf[nt][s][1] = cvt_f16x2(khi.x, khi.y);
                }
            }
        }
        const uint32_t a_base = smem_u32(smem) + OFF_B + (lane & 15) * 128 + (lane >> 4) * 16;
        const int r0 = lane >> 2;
        #pragma unroll 1
        for (int jb = warp * 4; jb < warp * 4 + 4; jb++) {
            uint32_t Af[4][4];
            #pragma unroll
            for (int s = 0; s < 4; s++) {
                asm volatile(
                    "ldmatrix.sync.aligned.m8n8.x4.shared.b16 {%0,%1,%2,%3}, [%4];"
                    : "=r"(Af[s][0]), "=r"(Af[s][1]), "=r"(Af[s][2]), "=r"(Af[s][3])
                    : "r"(a_base + jb * 2048 + s * 32));
            }
            float D[8][4] = {};
            #pragma unroll
            for (int s = 0; s < 4; s++)
                #pragma unroll
                for (int nt = 0; nt < 8; nt++)
                    mma_f16(D[nt], Af[s][0], Af[s][1], Af[s][2], Af[s][3],
                            Wf[nt][s][0], Wf[nt][s][1]);
            #pragma unroll
            for (int nt = 0; nt < 8; nt++) {
                int m0 = nt * 8 + (lane & 3) * 2;
                #pragma unroll
                for (int q = 0; q < 4; q++) {
                    int r = r0 + (q >> 1) * 8;
                    int m = m0 + (q & 1);
                    int off = OFF_B + jb * 2048 + nt * 256 + (m & 7) * 32
                            + ((r & 7) >> 1) * 8 + (r >> 3) * 4 + (r & 1) * 2;
                    *(__half*)(smem + off) = __float2half(D[nt][q]);
                }
            }
        }
    }
    __syncthreads();

    // ---- MMA phase: 2 row-passes x (2 mt x 8 nt), k16 skip ----
    const int g4 = lane >> 2;
    float cs[8][2] = {};

    #pragma unroll 1
    for (int rp = 0; rp < 2; rp++) {
        const int R = rp * 512 + warp * 32;

        u64 kmask = 0;
        {
            int rb0 = binof[R], rb1 = binof[R + 31];
            for (int b = rb0; b <= rb1; b++) kmask |= bkm[b];
        }

        u64 npx[4], npy[4];
        #pragma unroll
        for (int q = 0; q < 4; q++) {
            int i = R + (q >> 1) * 16 + g4 + (q & 1) * 8;
            npx[q] = pack2f(-px[i], -px[i]);
            npy[q] = pack2f(-py[i], -py[i]);
        }

        float acc[2][8][4] = {};
        #pragma unroll 1
        for (int k16 = 0; k16 < 64; k16++) {
            if (!((kmask >> k16) & 1ull)) continue;
            int jA = k16 * 16 + (lane & 3) * 2;
            u64 pax = ld2(px + jA),     pay = ld2(py + jA);
            u64 pbx = ld2(px + jA + 8), pby = ld2(py + jA + 8);

            uint32_t A[2][4];
            #pragma unroll
            for (int mt = 0; mt < 2; mt++) {
                A[mt][0] = maskpair(pax, pay, npx[mt*2],   npy[mt*2],   one2, nthr2);
                A[mt][1] = maskpair(pax, pay, npx[mt*2+1], npy[mt*2+1], one2, nthr2);
                A[mt][2] = maskpair(pbx, pby, npx[mt*2],   npy[mt*2],   one2, nthr2);
                A[mt][3] = maskpair(pbx, pby, npx[mt*2+1], npy[mt*2+1], one2, nthr2);
            }
            #pragma unroll
            for (int nt = 0; nt < 8; nt++) {
                uint2 bv = *(const uint2*)(smem + OFF_B + k16 * 2048 + nt * 256 + lane * 8);
                mma_f16(acc[0][nt], A[0][0], A[0][1], A[0][2], A[0][3], bv.x, bv.y);
                mma_f16(acc[1][nt], A[1][0], A[1][1], A[1][2], A[1][3], bv.x, bv.y);
            }
        }

        #pragma unroll
        for (int mt = 0; mt < 2; mt++) {
            float di0 = dinv[R + mt*16 + g4];
            float di1 = dinv[R + mt*16 + g4 + 8];
            #pragma unroll
            for (int nt = 0; nt < 8; nt++) {
                int col0 = nt * 8 + (lane & 3) * 2;
                float b20 = b2s[col0], b21 = b2s[col0 + 1];
                cs[nt][0] += fmaxf(fmaf(di0, acc[mt][nt][0], b20), 0.f);
                cs[nt][1] += fmaxf(fmaf(di0, acc[mt][nt][1], b21), 0.f);
                cs[nt][0] += fmaxf(fmaf(di1, acc[mt][nt][2], b20), 0.f);
                cs[nt][1] += fmaxf(fmaf(di1, acc[mt][nt][3], b21), 0.f);
            }
        }
    }

    #pragma unroll
    for (int nt = 0; nt < 8; nt++)
        #pragma unroll
        for (int p = 0; p < 2; p++) {
            float v = cs[nt][p];
            v += __shfl_xor_sync(0xffffffffu, v, 4);
            v += __shfl_xor_sync(0xffffffffu, v, 8);
            v += __shfl_xor_sync(0xffffffffu, v, 16);
            if (lane < 4)
                atomicAdd(&colsum[nt * 8 + lane * 2 + p], v);
        }
    __syncthreads();

    if (tid < 64) {
        float acc2 = bg[tid];
        const float inv = 1.0f / 1024.f;
        #pragma unroll 8
        for (int m = 0; m < 64; m++)
            acc2 = fmaf(colsum[m] * inv, Wg[tid * 64 + m], acc2);
        gcnv[tid] = acc2;
    }
    __syncthreads();
    if (tid < 384) {
        float acc2 = bih[tid];
        const float* wr = Wih + tid * 64;
        #pragma unroll 8
        for (int c2 = 0; c2 < 64; c2++)
            acc2 = fmaf(wr[c2], gcnv[c2], acc2);
        g_gi[g * 384 + tid] = acc2;
    }
}

// ---------------- GRU kernel: r9 register variant, gi direct global loads ----------------
__global__ void __launch_bounds__(384, 1) gru_kernel(
    const float* __restrict__ Whh, const float* __restrict__ bhh,
    const float* __restrict__ Wf,  const float* __restrict__ bf,
    float* __restrict__ out)
{
    __shared__ __align__(16) float h[128];
    __shared__ float gh_s[384];
    __shared__ float hsum_s[128];

    const int b   = blockIdx.x;
    const int tid = threadIdx.x;

    u64 wreg[64];
    const u64* wg = (const u64*)Whh;
    #pragma unroll
    for (int c2 = 0; c2 < 64; c2++) wreg[c2] = wg[tid * 64 + c2];

    if (tid < 128) h[tid] = 0.f;
    const float bhh_r = bhh[tid];
    const float* gib = g_gi + (size_t)b * 32 * 384;
    float hsum = 0.f;

    // gate threads prefetch their 3 gi values directly from global
    float giA = 0.f, giB = 0.f, giC = 0.f;
    if (tid < 128) {
        giA = gib[tid];
        giB = gib[128 + tid];
        giC = gib[256 + tid];
    }
    __syncthreads();

    for (int t = 0; t < 32; t++) {
        // gh[tid] = Whh[tid].h + bhh[tid] (fp32, packed f32x2)
        u64 acc2 = pack2f(bhh_r, 0.f);
        const double2* hv4 = (const double2*)h;
        #pragma unroll
        for (int c4 = 0; c4 < 32; c4++) {
            double2 hv = hv4[c4];
            FMA2(acc2, wreg[2*c4],     __double_as_longlong(hv.x));
            FMA2(acc2, wreg[2*c4 + 1], __double_as_longlong(hv.y));
        }
        float alo, ahi;
        asm("mov.b64 {%0, %1}, %2;" : "=f"(alo), "=f"(ahi) : "l"(acc2));
        gh_s[tid] = alo + ahi;

        // prefetch next step's gi (latency covered by barrier + gates)
        float nA = 0.f, nB = 0.f, nC = 0.f;
        if (t < 31 && tid < 128) {
            const float* gn = gib + (t + 1) * 384;
            nA = gn[tid];
            nB = gn[128 + tid];
            nC = gn[256 + tid];
        }
        __syncthreads();

        if (tid < 128) {
            float rg = 1.f / (1.f + __expf(-(giA + gh_s[tid])));
            float zg = 1.f / (1.f + __expf(-(giB + gh_s[128 + tid])));
            float ng = tanhf(giC + rg * gh_s[256 + tid]);
            float hn = (1.f - zg) * ng + zg * h[tid];
            h[tid] = hn;
            hsum += hn;
        }
        __syncthreads();
        giA = nA; giB = nB; giC = nC;
    }

    if (tid < 128) hsum_s[tid] = hsum;
    __syncthreads();
    if (tid < 2) {
        float acc = bf[tid];
        const float inv = 1.0f / 32.f;
        #pragma unroll 8
        for (int c = 0; c < 128; c++)
            acc = fmaf(Wf[tid * 128 + c], hsum_s[c] * inv, acc);
        out[b * 2 + tid] = acc;
    }
}

extern "C" void kernel_launch(void* const* d_in, const int* in_sizes, int n_in,
                              void* d_out, int out_size) {
    const float* points = (const float*)d_in[0];
    const float* W1  = (const float*)d_in[1];
    const float* b1  = (const float*)d_in[2];
    const float* W2  = (const float*)d_in[3];
    const float* b2  = (const float*)d_in[4];
    const float* Wg  = (const float*)d_in[5];
    const float* bg  = (const float*)d_in[6];
    const float* Wih = (const float*)d_in[7];
    const float* Whh = (const float*)d_in[8];
    const float* bih = (const float*)d_in[9];
    const float* bhh = (const float*)d_in[10];
    const float* Wf  = (const float*)d_in[11];
    const float* bf  = (const float*)d_in[12];
    float* out = (float*)d_out;

    cudaFuncSetAttribute(gcn_kernel, cudaFuncAttributeMaxDynamicSharedMemorySize, SMEM_GCN);

    gcn_kernel<<<128, NTH, SMEM_GCN>>>(points, W1, b1, W2, b2, Wg, bg, Wih, bih);
    gru_kernel<<<4, 384>>>(Whh, bhh, Wf, bf, out);
}

// round 17
// speedup vs baseline: 1.1444x; 1.0889x over previous
#include <cuda_runtime.h>
#include <cuda_bf16.h>
#include <cuda_fp16.h>
#include <stdint.h>

#define NPTS 1024
#define NTH  512
#define THR2 0.09f

typedef unsigned long long u64;

// ---------------- smem byte-offset map (GCN kernel) ----------------
// OFF_B dual use: x1 fp16 [1024][64] rows (j*128B), then in-place
// B fragments (fp16): [k16(64)][nt(8)][lane(32)][8B] = 128KB
#define OFF_B     0
#define OFF_PX    131072
#define OFF_PY    135168
#define OFF_DINV  139264
#define OFF_SX    143360
#define OFF_SY    147456
#define OFF_W2    151552   // 16KB
#define OFF_W1    167936   // 512B
#define OFF_B1    168448
#define OFF_B2    168704
#define OFF_CS    168960
#define OFF_GV    169216
#define OFF_BINOF 169472   // 1024 u8: bin of sorted point
#define OFF_BINST 170496   // 10 ints
#define OFF_CNT   170536   // 9 ints
#define OFF_CNT2  170572   // 9 ints
#define OFF_BKM   170608   // 9 u64 (8B aligned)
#define SMEM_GCN  170688

__device__ float g_gi[128 * 384];

// ---------------- helpers ----------------
__device__ __forceinline__ uint32_t smem_u32(const void* p) {
    uint32_t a;
    asm("{ .reg .u64 t; cvta.to.shared.u64 t, %1; cvt.u32.u64 %0, t; }" : "=r"(a) : "l"(p));
    return a;
}
__device__ __forceinline__ u64 pack2f(float a, float b) {
    u64 r; asm("mov.b64 %0, {%1, %2};" : "=l"(r) : "f"(a), "f"(b)); return r;
}
__device__ __forceinline__ u64 ld2(const float* p) {
    float2 v = *(const float2*)p;
    return pack2f(v.x, v.y);
}
#define FMA2(acc, a, b) asm("fma.rn.f32x2 %0, %1, %2, %0;" : "+l"(acc) : "l"(a), "l"(b))
__device__ __forceinline__ u64 add2(u64 a, u64 b) {
    u64 r; asm("add.rn.f32x2 %0, %1, %2;" : "=l"(r) : "l"(a), "l"(b)); return r;
}
__device__ __forceinline__ u64 fma2v(u64 a, u64 b, u64 c) {
    u64 r; asm("fma.rn.f32x2 %0, %1, %2, %3;" : "=l"(r) : "l"(a), "l"(b), "l"(c)); return r;
}
// pack two f32 into f16x2: lo = a (even k), hi = b (odd k)
__device__ __forceinline__ uint32_t cvt_f16x2(float a, float b) {
    uint32_t r;
    asm("cvt.rn.f16x2.f32 %0, %1, %2;" : "=r"(r) : "f"(b), "f"(a));
    return r;
}
// mask pair: fp16x2 {adj(i,j0), adj(i,j1)}; u = dx^2 + dy^2 - thr2, neighbor <=> sign(u)
__device__ __forceinline__ uint32_t maskpair(u64 px2, u64 py2, u64 nx2, u64 ny2,
                                             u64 one2, u64 nthr2) {
    u64 dx, dy, u;
    asm("fma.rn.f32x2 %0, %1, %2, %3;" : "=l"(dx) : "l"(px2), "l"(one2), "l"(nx2));
    asm("fma.rn.f32x2 %0, %1, %2, %3;" : "=l"(dy) : "l"(py2), "l"(one2), "l"(ny2));
    asm("fma.rn.f32x2 %0, %1, %1, %2;" : "=l"(u)  : "l"(dy), "l"(nthr2));
    asm("fma.rn.f32x2 %0, %1, %1, %0;" : "+l"(u)  : "l"(dx));
    uint32_t lo, hi, m;
    asm("mov.b64 {%0, %1}, %2;" : "=r"(lo), "=r"(hi) : "l"(u));
    asm("prmt.b32 %0, %1, %2, 0xFFBB;" : "=r"(m) : "r"(lo), "r"(hi));
    return m & 0x3C003C00u;
}
__device__ __forceinline__ void mma_f16(float* d, uint32_t a0, uint32_t a1,
                                        uint32_t a2, uint32_t a3,
                                        uint32_t b0, uint32_t b1) {
    asm("mma.sync.aligned.m16n8k16.row.col.f32.f16.f16.f32 "
        "{%0,%1,%2,%3}, {%4,%5,%6,%7}, {%8,%9}, {%0,%1,%2,%3};"
        : "+f"(d[0]), "+f"(d[1]), "+f"(d[2]), "+f"(d[3])
        : "r"(a0), "r"(a1), "r"(a2), "r"(a3), "r"(b0), "r"(b1));
}
__device__ __forceinline__ uint32_t neigh9(int b) {
    int by = b / 3, bx = b - by * 3;
    int y0 = by > 0 ? by - 1 : 0, y1 = by < 2 ? by + 1 : 2;
    int x0 = bx > 0 ? bx - 1 : 0, x1 = bx < 2 ? bx + 1 : 2;
    uint32_t m = 0;
    for (int yy = y0; yy <= y1; yy++)
        for (int xx = x0; xx <= x1; xx++) m |= 1u << (yy * 3 + xx);
    return m;
}

// ---------------- GCN kernel ----------------
__global__ void __launch_bounds__(NTH, 1) gcn_kernel(
    const float* __restrict__ points,
    const float* __restrict__ W1, const float* __restrict__ b1,
    const float* __restrict__ W2, const float* __restrict__ b2,
    const float* __restrict__ Wg, const float* __restrict__ bg,
    const float* __restrict__ Wih, const float* __restrict__ bih)
{
    extern __shared__ char smem[];
    float* px   = (float*)(smem + OFF_PX);
    float* py   = (float*)(smem + OFF_PY);
    float* dinv = (float*)(smem + OFF_DINV);
    float* sx   = (float*)(smem + OFF_SX);
    float* sy   = (float*)(smem + OFF_SY);
    float* w2s  = (float*)(smem + OFF_W2);
    float* w1s  = (float*)(smem + OFF_W1);
    float* b1s  = (float*)(smem + OFF_B1);
    float* b2s  = (float*)(smem + OFF_B2);
    float* colsum = (float*)(smem + OFF_CS);
    float* gcnv   = (float*)(smem + OFF_GV);
    uint8_t* binof = (uint8_t*)(smem + OFF_BINOF);
    int* binstart  = (int*)(smem + OFF_BINST);
    int* counts    = (int*)(smem + OFF_CNT);
    int* cnt2      = (int*)(smem + OFF_CNT2);
    u64* bkm       = (u64*)(smem + OFF_BKM);

    const int g    = blockIdx.x;
    const int tid  = threadIdx.x;
    const int lane = tid & 31;
    const int warp = tid >> 5;

    const float* pts = points + (size_t)g * NPTS * 2;
    for (int j = tid; j < NPTS; j += NTH) {
        float2 p = ((const float2*)pts)[j];
        sx[j] = p.x; sy[j] = p.y;
    }
    for (int i = tid; i < 128; i += NTH)  w1s[i] = W1[i];
    for (int i = tid; i < 4096; i += NTH) w2s[i] = W2[i];
    if (tid < 64) { b1s[tid] = b1[tid]; b2s[tid] = b2[tid]; colsum[tid] = 0.f; }
    if (tid < 9) { counts[tid] = 0; cnt2[tid] = 0; }
    __syncthreads();

    for (int ig = 0; ig < 2; ig++) {
        int j = tid + ig * NTH;
        int bx = (int)(sx[j] * 3.0f); bx = bx > 2 ? 2 : bx;
        int by = (int)(sy[j] * 3.0f); by = by > 2 ? 2 : by;
        atomicAdd(&counts[by * 3 + bx], 1);
    }
    __syncthreads();
    if (tid == 0) {
        int acc = 0;
        for (int b = 0; b < 9; b++) { binstart[b] = acc; acc += counts[b]; }
        binstart[9] = acc;
    }
    __syncthreads();

    for (int ig = 0; ig < 2; ig++) {
        int j = tid + ig * NTH;
        float x = sx[j], y = sy[j];
        int bx = (int)(x * 3.0f); bx = bx > 2 ? 2 : bx;
        int by = (int)(y * 3.0f); by = by > 2 ? 2 : by;
        int b = by * 3 + bx;
        int rank = binstart[b] + atomicAdd(&cnt2[b], 1);
        px[rank] = x; py[rank] = y;
        binof[rank] = (uint8_t)b;
    }
    __syncthreads();

    if (tid < 9) {
        uint32_t alw = neigh9(tid);
        u64 m = 0;
        for (int k = 0; k < 64; k++) {
            int c0 = binof[k * 16], c1 = binof[k * 16 + 15];
            uint32_t rng = ((2u << c1) - 1u) & ~((1u << c0) - 1u);
            if (alw & rng) m |= 1ull << k;
        }
        bkm[tid] = m;
    }

    const u64 one2  = pack2f(1.f, 1.f);
    const u64 nthr2 = pack2f(-THR2, -THR2);
    const u64* pxp = (const u64*)px;
    const u64* pyp = (const u64*)py;
    __syncthreads();

    // =============== deg + s with WARP-UNIFORM band segments ===============
    // Warp w (pass ig) owns rows [w*32 + ig*512, +32). Rows are bin-sorted, so
    // the warp's bins span [binof[W0], binof[W0+31]]. Segments are the union of
    // allowed neighborhoods over that bin interval — identical for all lanes
    // (zero divergence). Supersets are safe: the exact distance test rejects
    // strays, contributing exact zeros.

    // ---- degree pass ----
    for (int ig = 0; ig < 2; ig++) {
        const int W0 = (warp + ig * 16) * 32;
        const int i  = W0 + lane;
        // warp-uniform allowed-bin mask
        uint32_t alw = 0;
        {
            int b0 = binof[W0], b1x = binof[W0 + 31];
            for (int b = b0; b <= b1x; b++) alw |= neigh9(b);
        }
        // warp-uniform segments (up to 3 bands), with monotone `last` guard
        int lps[3], hps[3];
        {
            int last = -1;
            #pragma unroll
            for (int band = 0; band < 3; band++) {
                uint32_t bm = (alw >> (band * 3)) & 7u;
                if (bm) {
                    int xlo = (bm & 1u) ? 0 : ((bm & 2u) ? 1 : 2);
                    int xhi = (bm & 4u) ? 2 : ((bm & 2u) ? 1 : 0);
                    int l = binstart[band * 3 + xlo] >> 1;
                    if (l <= last) l = last + 1;
                    int h = (binstart[band * 3 + xhi + 1] + 1) >> 1;
                    lps[band] = l; hps[band] = h;
                    if (h - 1 > last) last = h - 1;
                } else { lps[band] = 0; hps[band] = 0; }
            }
        }
        u64 nxi = pack2f(-px[i], -px[i]);
        u64 nyi = pack2f(-py[i], -py[i]);
        uint32_t acc_h = 0;
        #pragma unroll 1
        for (int seg = 0; seg < 3; seg++) {
            #pragma unroll 4
            for (int jp = lps[seg]; jp < hps[seg]; jp++) {
                uint32_t m = maskpair(pxp[jp], pyp[jp], nxi, nyi, one2, nthr2);
                asm("add.rn.f16x2 %0, %0, %1;" : "+r"(acc_h) : "r"(m));
            }
        }
        __half2 h2 = *(__half2*)&acc_h;
        dinv[i] = rsqrtf(__low2float(h2) + __high2float(h2));
    }
    __syncthreads();

    // ---- s pass ----
    const u64* dvp = (const u64*)dinv;
    for (int ig = 0; ig < 2; ig++) {
        const int W0 = (warp + ig * 16) * 32;
        const int i  = W0 + lane;
        uint32_t alw = 0;
        {
            int b0 = binof[W0], b1x = binof[W0 + 31];
            for (int b = b0; b <= b1x; b++) alw |= neigh9(b);
        }
        int lps[3], hps[3];
        {
            int last = -1;
            #pragma unroll
            for (int band = 0; band < 3; band++) {
                uint32_t bm = (alw >> (band * 3)) & 7u;
                if (bm) {
                    int xlo = (bm & 1u) ? 0 : ((bm & 2u) ? 1 : 2);
                    int xhi = (bm & 4u) ? 2 : ((bm & 2u) ? 1 : 0);
                    int l = binstart[band * 3 + xlo] >> 1;
                    if (l <= last) l = last + 1;
                    int h = (binstart[band * 3 + xhi + 1] + 1) >> 1;
                    lps[band] = l; hps[band] = h;
                    if (h - 1 > last) last = h - 1;
                } else { lps[band] = 0; hps[band] = 0; }
            }
        }
        u64 nxi = pack2f(-px[i], -px[i]);
        u64 nyi = pack2f(-py[i], -py[i]);
        u64 ax2 = 0ULL, ay2 = 0ULL;
        #pragma unroll 1
        for (int seg = 0; seg < 3; seg++) {
            #pragma unroll 4
            for (int jp = lps[seg]; jp < hps[seg]; jp++) {
                u64 px2 = pxp[jp], py2 = pyp[jp];
                u64 dx2 = add2(px2, nxi);
                u64 dy2 = add2(py2, nyi);
                u64 u = fma2v(dy2, dy2, nthr2);
                FMA2(u, dx2, dx2);
                uint32_t mlo = (uint32_t)(((int32_t)(uint32_t)u) >> 31);
                uint32_t mhi = (uint32_t)(((int32_t)(uint32_t)(u >> 32)) >> 31);
                u64 dv = dvp[jp];
                u64 m2 = (u64)((uint32_t)dv & mlo) | (((u64)((uint32_t)(dv >> 32) & mhi)) << 32);
                FMA2(ax2, m2, px2);
                FMA2(ay2, m2, py2);
            }
        }
        float axl, axh, ayl, ayh;
        asm("mov.b64 {%0, %1}, %2;" : "=f"(axl), "=f"(axh) : "l"(ax2));
        asm("mov.b64 {%0, %1}, %2;" : "=f"(ayl), "=f"(ayh) : "l"(ay2));
        float di = dinv[i];
        sx[i] = di * (axl + axh);
        sy[i] = di * (ayl + ayh);
    }
    __syncthreads();

    // ---- B-build phase 1: x1 fp16 rows into OFF_B ----
    #pragma unroll 1
    for (int half = 0; half < 2; half++) {
        int j = tid + half * 512;
        float s0 = sx[j], s1 = sy[j], dj = dinv[j];
        uint32_t row[32];
        #pragma unroll
        for (int k2 = 0; k2 < 32; k2++) {
            float a = fmaxf(fmaf(s0, w1s[4*k2],   fmaf(s1, w1s[4*k2+1], b1s[2*k2])),   0.f) * dj;
            float b = fmaxf(fmaf(s0, w1s[4*k2+2], fmaf(s1, w1s[4*k2+3], b1s[2*k2+1])), 0.f) * dj;
            row[k2] = cvt_f16x2(a, b);
        }
        uint4* dst = (uint4*)(smem + OFF_B + j * 128);
        #pragma unroll
        for (int q = 0; q < 8; q++)
            dst[q] = make_uint4(row[4*q], row[4*q+1], row[4*q+2], row[4*q+3]);
    }
    __syncthreads();

    // ---- B-build phase 2: w = x1 @ W2^T via HMMA, in-place scatter ----
    {
        uint32_t Wf[8][4][2];
        {
            int m = (lane >> 2);
            int kq = (lane & 3) * 2;
            #pragma unroll
            for (int nt = 0; nt < 8; nt++) {
                const float* wr = w2s + (nt * 8 + m) * 64;
                #pragma unroll
                for (int s = 0; s < 4; s++) {
                    float2 klo = *(const float2*)(wr + s * 16 + kq);
                    float2 khi = *(const float2*)(wr + s * 16 + kq + 8);
                    Wf[nt][s][0] = cvt_f16x2(klo.x, klo.y);
                    Wf[nt][s][1] = cvt_f16x2(khi.x, khi.y);
                }
            }
        }
        const uint32_t a_base = smem_u32(smem) + OFF_B + (lane & 15) * 128 + (lane >> 4) * 16;
        const int r0 = lane >> 2;
        #pragma unroll 1
        for (int jb = warp * 4; jb < warp * 4 + 4; jb++) {
            uint32_t Af[4][4];
            #pragma unroll
            for (int s = 0; s < 4; s++) {
                asm volatile(
                    "ldmatrix.sync.aligned.m8n8.x4.shared.b16 {%0,%1,%2,%3}, [%4];"
                    : "=r"(Af[s][0]), "=r"(Af[s][1]), "=r"(Af[s][2]), "=r"(Af[s][3])
                    : "r"(a_base + jb * 2048 + s * 32));
            }
            float D[8][4] = {};
            #pragma unroll
            for (int s = 0; s < 4; s++)
                #pragma unroll
                for (int nt = 0; nt < 8; nt++)
                    mma_f16(D[nt], Af[s][0], Af[s][1], Af[s][2], Af[s][3],
                            Wf[nt][s][0], Wf[nt][s][1]);
            #pragma unroll
            for (int nt = 0; nt < 8; nt++) {
                int m0 = nt * 8 + (lane & 3) * 2;
                #pragma unroll
                for (int q = 0; q < 4; q++) {
                    int r = r0 + (q >> 1) * 8;
                    int m = m0 + (q & 1);
                    int off = OFF_B + jb * 2048 + nt * 256 + (m & 7) * 32
                            + ((r & 7) >> 1) * 8 + (r >> 3) * 4 + (r & 1) * 2;
                    *(__half*)(smem + off) = __float2half(D[nt][q]);
                }
            }
        }
    }
    __syncthreads();

    // ---- MMA phase: 2 row-passes x (2 mt x 8 nt), k16 skip ----
    const int g4 = lane >> 2;
    float cs[8][2] = {};

    #pragma unroll 1
    for (int rp = 0; rp < 2; rp++) {
        const int R = rp * 512 + warp * 32;

        u64 kmask = 0;
        {
            int rb0 = binof[R], rb1 = binof[R + 31];
            for (int b = rb0; b <= rb1; b++) kmask |= bkm[b];
        }

        u64 npx[4], npy[4];
        #pragma unroll
        for (int q = 0; q < 4; q++) {
            int i = R + (q >> 1) * 16 + g4 + (q & 1) * 8;
            npx[q] = pack2f(-px[i], -px[i]);
            npy[q] = pack2f(-py[i], -py[i]);
        }

        float acc[2][8][4] = {};
        #pragma unroll 1
        for (int k16 = 0; k16 < 64; k16++) {
            if (!((kmask >> k16) & 1ull)) continue;
            int jA = k16 * 16 + (lane & 3) * 2;
            u64 pax = ld2(px + jA),     pay = ld2(py + jA);
            u64 pbx = ld2(px + jA + 8), pby = ld2(py + jA + 8);

            uint32_t A[2][4];
            #pragma unroll
            for (int mt = 0; mt < 2; mt++) {
                A[mt][0] = maskpair(pax, pay, npx[mt*2],   npy[mt*2],   one2, nthr2);
                A[mt][1] = maskpair(pax, pay, npx[mt*2+1], npy[mt*2+1], one2, nthr2);
                A[mt][2] = maskpair(pbx, pby, npx[mt*2],   npy[mt*2],   one2, nthr2);
                A[mt][3] = maskpair(pbx, pby, npx[mt*2+1], npy[mt*2+1], one2, nthr2);
            }
            #pragma unroll
            for (int nt = 0; nt < 8; nt++) {
                uint2 bv = *(const uint2*)(smem + OFF_B + k16 * 2048 + nt * 256 + lane * 8);
                mma_f16(acc[0][nt], A[0][0], A[0][1], A[0][2], A[0][3], bv.x, bv.y);
                mma_f16(acc[1][nt], A[1][0], A[1][1], A[1][2], A[1][3], bv.x, bv.y);
            }
        }

        #pragma unroll
        for (int mt = 0; mt < 2; mt++) {
            float di0 = dinv[R + mt*16 + g4];
            float di1 = dinv[R + mt*16 + g4 + 8];
            #pragma unroll
            for (int nt = 0; nt < 8; nt++) {
                int col0 = nt * 8 + (lane & 3) * 2;
                float b20 = b2s[col0], b21 = b2s[col0 + 1];
                cs[nt][0] += fmaxf(fmaf(di0, acc[mt][nt][0], b20), 0.f);
                cs[nt][1] += fmaxf(fmaf(di0, acc[mt][nt][1], b21), 0.f);
                cs[nt][0] += fmaxf(fmaf(di1, acc[mt][nt][2], b20), 0.f);
                cs[nt][1] += fmaxf(fmaf(di1, acc[mt][nt][3], b21), 0.f);
            }
        }
    }

    #pragma unroll
    for (int nt = 0; nt < 8; nt++)
        #pragma unroll
        for (int p = 0; p < 2; p++) {
            float v = cs[nt][p];
            v += __shfl_xor_sync(0xffffffffu, v, 4);
            v += __shfl_xor_sync(0xffffffffu, v, 8);
            v += __shfl_xor_sync(0xffffffffu, v, 16);
            if (lane < 4)
                atomicAdd(&colsum[nt * 8 + lane * 2 + p], v);
        }
    __syncthreads();

    if (tid < 64) {
        float acc2 = bg[tid];
        const float inv = 1.0f / 1024.f;
        #pragma unroll 8
        for (int m = 0; m < 64; m++)
            acc2 = fmaf(colsum[m] * inv, Wg[tid * 64 + m], acc2);
        gcnv[tid] = acc2;
    }
    __syncthreads();
    if (tid < 384) {
        float acc2 = bih[tid];
        const float* wr = Wih + tid * 64;
        #pragma unroll 8
        for (int c2 = 0; c2 < 64; c2++)
            acc2 = fmaf(wr[c2], gcnv[c2], acc2);
        g_gi[g * 384 + tid] = acc2;
    }
}

// ---------------- GRU kernel: r9-exact (frozen, 40.7us) ----------------
__global__ void __launch_bounds__(384, 1) gru_kernel(
    const float* __restrict__ Whh, const float* __restrict__ bhh,
    const float* __restrict__ Wf,  const float* __restrict__ bf,
    float* __restrict__ out)
{
    __shared__ __align__(16) float h[128];
    __shared__ float gh_s[384];
    __shared__ float gi_s[384];
    __shared__ float hsum_s[128];

    const int b   = blockIdx.x;
    const int tid = threadIdx.x;

    u64 wreg[64];
    const u64* wg = (const u64*)Whh;
    #pragma unroll
    for (int c2 = 0; c2 < 64; c2++) wreg[c2] = wg[tid * 64 + c2];

    if (tid < 128) h[tid] = 0.f;
    const float bhh_r = bhh[tid];
    const float* gib = g_gi + (size_t)b * 32 * 384;
    float gi_cur = gib[tid];
    float hsum = 0.f;
    __syncthreads();

    for (int t = 0; t < 32; t++) {
        float gi_nxt = (t < 31) ? gib[(t + 1) * 384 + tid] : 0.f;
        gi_s[tid] = gi_cur;

        u64 acc2 = pack2f(bhh_r, 0.f);
        const double2* hv4 = (const double2*)h;
        #pragma unroll
        for (int c4 = 0; c4 < 32; c4++) {
            double2 hv = hv4[c4];
            FMA2(acc2, wreg[2*c4],     __double_as_longlong(hv.x));
            FMA2(acc2, wreg[2*c4 + 1], __double_as_longlong(hv.y));
        }
        float alo, ahi;
        asm("mov.b64 {%0, %1}, %2;" : "=f"(alo), "=f"(ahi) : "l"(acc2));
        gh_s[tid] = alo + ahi;
        __syncthreads();

        if (tid < 128) {
            float rg = 1.f / (1.f + __expf(-(gi_s[tid]       + gh_s[tid])));
            float zg = 1.f / (1.f + __expf(-(gi_s[128 + tid] + gh_s[128 + tid])));
            float ng = tanhf(gi_s[256 + tid] + rg * gh_s[256 + tid]);
            float hn = (1.f - zg) * ng + zg * h[tid];
            h[tid] = hn;
            hsum += hn;
        }
        __syncthreads();
        gi_cur = gi_nxt;
    }

    if (tid < 128) hsum_s[tid] = hsum;
    __syncthreads();
    if (tid < 2) {
        float acc = bf[tid];
        const float inv = 1.0f / 32.f;
        #pragma unroll 8
        for (int c = 0; c < 128; c++)
            acc = fmaf(Wf[tid * 128 + c], hsum_s[c] * inv, acc);
        out[b * 2 + tid] = acc;
    }
}

extern "C" void kernel_launch(void* const* d_in, const int* in_sizes, int n_in,
                              void* d_out, int out_size) {
    const float* points = (const float*)d_in[0];
    const float* W1  = (const float*)d_in[1];
    const float* b1  = (const float*)d_in[2];
    const float* W2  = (const float*)d_in[3];
    const float* b2  = (const float*)d_in[4];
    const float* Wg  = (const float*)d_in[5];
    const float* bg  = (const float*)d_in[6];
    const float* Wih = (const float*)d_in[7];
    const float* Whh = (const float*)d_in[8];
    const float* bih = (const float*)d_in[9];
    const float* bhh = (const float*)d_in[10];
    const float* Wf  = (const float*)d_in[11];
    const float* bf  = (const float*)d_in[12];
    float* out = (float*)d_out;

    cudaFuncSetAttribute(gcn_kernel, cudaFuncAttributeMaxDynamicSharedMemorySize, SMEM_GCN);

    gcn_kernel<<<128, NTH, SMEM_GCN>>>(points, W1, b1, W2, b2, Wg, bg, Wih, bih);
    gru_kernel<<<4, 384>>>(Whh, bhh, Wf, bf, out);
}